// round 1
// baseline (speedup 1.0000x reference)
#include <cuda_runtime.h>
#include <math.h>

#define BB   2
#define SEQ  2048
#define DIM  1024
#define HEADS 16
#define DKH  64
#define MTOT (BB * SEQ * DIM)   // 4096*1024

// Scratch (allocation-free rule: __device__ globals)
__device__ float g_q[MTOT];
__device__ float g_k[MTOT];
__device__ float g_v[MTOT];
__device__ float g_blend[MTOT];

// ---------------------------------------------------------------------------
// C[M,N] = A[M,K] @ W[N,K]^T + bias[N]       (both operands K-contiguous)
// BM=BN=128, BK=8, 256 threads, 8x8 microtile
// ---------------------------------------------------------------------------
__global__ __launch_bounds__(256) void gemm_nt_bias(
    const float* __restrict__ A, const float* __restrict__ W,
    const float* __restrict__ bias, float* __restrict__ C,
    int M, int N, int K)
{
    __shared__ float As[8][128];
    __shared__ float Ws[8][128];
    const int tid = threadIdx.x;
    const int bm = blockIdx.y * 128;
    const int bn = blockIdx.x * 128;
    const int lr = tid >> 1;            // 0..127
    const int lc = (tid & 1) << 2;      // 0 or 4
    const int tm = (tid >> 4) << 3;     // row of microtile
    const int tn = (tid & 15) << 3;     // col of microtile
    float acc[8][8] = {};
    const float* Ap = A + (size_t)(bm + lr) * K + lc;
    const float* Wp = W + (size_t)(bn + lr) * K + lc;

    for (int k0 = 0; k0 < K; k0 += 8) {
        float4 a4 = *(const float4*)(Ap + k0);
        float4 w4 = *(const float4*)(Wp + k0);
        As[lc + 0][lr] = a4.x; As[lc + 1][lr] = a4.y;
        As[lc + 2][lr] = a4.z; As[lc + 3][lr] = a4.w;
        Ws[lc + 0][lr] = w4.x; Ws[lc + 1][lr] = w4.y;
        Ws[lc + 2][lr] = w4.z; Ws[lc + 3][lr] = w4.w;
        __syncthreads();
#pragma unroll
        for (int k = 0; k < 8; k++) {
            float ra[8], rb[8];
            *(float4*)(ra)     = *(const float4*)&As[k][tm];
            *(float4*)(ra + 4) = *(const float4*)&As[k][tm + 4];
            *(float4*)(rb)     = *(const float4*)&Ws[k][tn];
            *(float4*)(rb + 4) = *(const float4*)&Ws[k][tn + 4];
#pragma unroll
            for (int i = 0; i < 8; i++)
#pragma unroll
                for (int j = 0; j < 8; j++)
                    acc[i][j] += ra[i] * rb[j];
        }
        __syncthreads();
    }

#pragma unroll
    for (int i = 0; i < 8; i++) {
#pragma unroll
        for (int j = 0; j < 8; j += 4) {
            float4 o;
            o.x = acc[i][j + 0] + bias[bn + tn + j + 0];
            o.y = acc[i][j + 1] + bias[bn + tn + j + 1];
            o.z = acc[i][j + 2] + bias[bn + tn + j + 2];
            o.w = acc[i][j + 3] + bias[bn + tn + j + 3];
            *(float4*)&C[(size_t)(bm + tm + i) * N + bn + tn + j] = o;
        }
    }
}

// ---------------------------------------------------------------------------
// scores[b,h,s,t] = (1/8) * sum_d q[b,s,h*64+d] * k[b,t,h*64+d]
// Per (b,h): GEMM 2048x2048x64, both K-contiguous with ld=DIM.
// ---------------------------------------------------------------------------
__global__ __launch_bounds__(256) void gemm_qk(
    const float* __restrict__ q, const float* __restrict__ k,
    float* __restrict__ scores)
{
    __shared__ float As[8][128];
    __shared__ float Bs[8][128];
    const int bh = blockIdx.z;
    const int b = bh >> 4, h = bh & 15;
    const float* A  = q + (size_t)b * SEQ * DIM + h * DKH;
    const float* Bm = k + (size_t)b * SEQ * DIM + h * DKH;
    float* C = scores + (size_t)bh * SEQ * SEQ;

    const int tid = threadIdx.x;
    const int bm = blockIdx.y * 128;
    const int bn = blockIdx.x * 128;
    const int lr = tid >> 1;
    const int lc = (tid & 1) << 2;
    const int tm = (tid >> 4) << 3;
    const int tn = (tid & 15) << 3;
    float acc[8][8] = {};
    const float* Ap = A  + (size_t)(bm + lr) * DIM + lc;
    const float* Bp = Bm + (size_t)(bn + lr) * DIM + lc;

    for (int k0 = 0; k0 < DKH; k0 += 8) {
        float4 a4 = *(const float4*)(Ap + k0);
        float4 b4 = *(const float4*)(Bp + k0);
        As[lc + 0][lr] = a4.x; As[lc + 1][lr] = a4.y;
        As[lc + 2][lr] = a4.z; As[lc + 3][lr] = a4.w;
        Bs[lc + 0][lr] = b4.x; Bs[lc + 1][lr] = b4.y;
        Bs[lc + 2][lr] = b4.z; Bs[lc + 3][lr] = b4.w;
        __syncthreads();
#pragma unroll
        for (int kk = 0; kk < 8; kk++) {
            float ra[8], rb[8];
            *(float4*)(ra)     = *(const float4*)&As[kk][tm];
            *(float4*)(ra + 4) = *(const float4*)&As[kk][tm + 4];
            *(float4*)(rb)     = *(const float4*)&Bs[kk][tn];
            *(float4*)(rb + 4) = *(const float4*)&Bs[kk][tn + 4];
#pragma unroll
            for (int i = 0; i < 8; i++)
#pragma unroll
                for (int j = 0; j < 8; j++)
                    acc[i][j] += ra[i] * rb[j];
        }
        __syncthreads();
    }

    const float scale = 0.125f;   // 1/sqrt(64)
#pragma unroll
    for (int i = 0; i < 8; i++) {
#pragma unroll
        for (int j = 0; j < 8; j += 4) {
            float4 o;
            o.x = acc[i][j + 0] * scale;
            o.y = acc[i][j + 1] * scale;
            o.z = acc[i][j + 2] * scale;
            o.w = acc[i][j + 3] * scale;
            *(float4*)&C[(size_t)(bm + tm + i) * SEQ + bn + tn + j] = o;
        }
    }
}

// ---------------------------------------------------------------------------
// In-place row softmax; one block per row of length 2048 (256 thr * 8 elems)
// ---------------------------------------------------------------------------
__global__ __launch_bounds__(256) void softmax2048(float* __restrict__ sc)
{
    float* row = sc + (size_t)blockIdx.x * SEQ;
    const int tid = threadIdx.x;
    float4 v0 = *(const float4*)(row + tid * 4);
    float4 v1 = *(const float4*)(row + 1024 + tid * 4);

    float m = fmaxf(fmaxf(fmaxf(v0.x, v0.y), fmaxf(v0.z, v0.w)),
                    fmaxf(fmaxf(v1.x, v1.y), fmaxf(v1.z, v1.w)));
#pragma unroll
    for (int off = 16; off > 0; off >>= 1)
        m = fmaxf(m, __shfl_xor_sync(0xffffffffu, m, off));
    __shared__ float sm[8];
    if ((tid & 31) == 0) sm[tid >> 5] = m;
    __syncthreads();
    float bmax = sm[0];
#pragma unroll
    for (int w = 1; w < 8; w++) bmax = fmaxf(bmax, sm[w]);

    v0.x = __expf(v0.x - bmax); v0.y = __expf(v0.y - bmax);
    v0.z = __expf(v0.z - bmax); v0.w = __expf(v0.w - bmax);
    v1.x = __expf(v1.x - bmax); v1.y = __expf(v1.y - bmax);
    v1.z = __expf(v1.z - bmax); v1.w = __expf(v1.w - bmax);

    float s = (v0.x + v0.y + v0.z + v0.w) + (v1.x + v1.y + v1.z + v1.w);
#pragma unroll
    for (int off = 16; off > 0; off >>= 1)
        s += __shfl_xor_sync(0xffffffffu, s, off);
    __shared__ float ss[8];
    if ((tid & 31) == 0) ss[tid >> 5] = s;
    __syncthreads();
    float tot = ss[0];
#pragma unroll
    for (int w = 1; w < 8; w++) tot += ss[w];
    float inv = 1.0f / tot;

    v0.x *= inv; v0.y *= inv; v0.z *= inv; v0.w *= inv;
    v1.x *= inv; v1.y *= inv; v1.z *= inv; v1.w *= inv;
    *(float4*)(row + tid * 4) = v0;
    *(float4*)(row + 1024 + tid * 4) = v1;
}

// ---------------------------------------------------------------------------
// blended[b,s,h*64+d] = sum_t P[b,h,s,t] * v[b,t,h*64+d]
// Per (b,h): GEMM M=2048, N=64, K=2048 (A K-contig ld=SEQ; B N-contig ld=DIM)
// BM=128, BN=64, BK=16, 256 threads, 8x4 microtile
// ---------------------------------------------------------------------------
__global__ __launch_bounds__(256) void gemm_pv(
    const float* __restrict__ scores, const float* __restrict__ v,
    float* __restrict__ blend)
{
    __shared__ float As[16][128];
    __shared__ float Bs[16][64];
    const int bh = blockIdx.z;
    const int b = bh >> 4, h = bh & 15;
    const float* A = scores + (size_t)bh * SEQ * SEQ;
    const float* V = v + (size_t)b * SEQ * DIM + h * DKH;
    float* C = blend + (size_t)b * SEQ * DIM + h * DKH;

    const int tid = threadIdx.x;
    const int bm = blockIdx.y * 128;
    const int ar = tid >> 2;            // 0..63
    const int ac = (tid & 3) << 2;      // 0,4,8,12
    const int br = tid >> 4;            // 0..15
    const int bc = (tid & 15) << 2;     // 0..60
    const int tm = (tid >> 4) << 3;
    const int tn = (tid & 15) << 2;
    float acc[8][4] = {};

    for (int k0 = 0; k0 < SEQ; k0 += 16) {
        float4 a0 = *(const float4*)(A + (size_t)(bm + ar) * SEQ + k0 + ac);
        float4 a1 = *(const float4*)(A + (size_t)(bm + ar + 64) * SEQ + k0 + ac);
        float4 b4 = *(const float4*)(V + (size_t)(k0 + br) * DIM + bc);
        As[ac + 0][ar] = a0.x; As[ac + 1][ar] = a0.y;
        As[ac + 2][ar] = a0.z; As[ac + 3][ar] = a0.w;
        As[ac + 0][ar + 64] = a1.x; As[ac + 1][ar + 64] = a1.y;
        As[ac + 2][ar + 64] = a1.z; As[ac + 3][ar + 64] = a1.w;
        *(float4*)&Bs[br][bc] = b4;
        __syncthreads();
#pragma unroll
        for (int kk = 0; kk < 16; kk++) {
            float ra[8], rb[4];
            *(float4*)(ra)     = *(const float4*)&As[kk][tm];
            *(float4*)(ra + 4) = *(const float4*)&As[kk][tm + 4];
            *(float4*)(rb)     = *(const float4*)&Bs[kk][tn];
#pragma unroll
            for (int i = 0; i < 8; i++)
#pragma unroll
                for (int j = 0; j < 4; j++)
                    acc[i][j] += ra[i] * rb[j];
        }
        __syncthreads();
    }

#pragma unroll
    for (int i = 0; i < 8; i++) {
        float4 o = { acc[i][0], acc[i][1], acc[i][2], acc[i][3] };
        *(float4*)&C[(size_t)(bm + tm + i) * DIM + tn] = o;
    }
}

// ---------------------------------------------------------------------------
extern "C" void kernel_launch(void* const* d_in, const int* in_sizes, int n_in,
                              void* d_out, int out_size)
{
    const float* query = (const float*)d_in[0];
    const float* key   = (const float*)d_in[1];
    const float* value = (const float*)d_in[2];
    const float* Wq = (const float*)d_in[3];
    const float* bq = (const float*)d_in[4];
    const float* Wk = (const float*)d_in[5];
    const float* bk = (const float*)d_in[6];
    const float* Wv = (const float*)d_in[7];
    const float* bv = (const float*)d_in[8];
    const float* Wo = (const float*)d_in[9];
    const float* bo = (const float*)d_in[10];

    float* out    = (float*)d_out;
    float* scores = out + (size_t)BB * SEQ * DIM;   // attention_score region

    float *qp, *kp, *vp, *bl;
    cudaGetSymbolAddress((void**)&qp, g_q);
    cudaGetSymbolAddress((void**)&kp, g_k);
    cudaGetSymbolAddress((void**)&vp, g_v);
    cudaGetSymbolAddress((void**)&bl, g_blend);

    dim3 gproj(DIM / 128, (BB * SEQ) / 128);        // (8, 32)
    gemm_nt_bias<<<gproj, 256>>>(query, Wq, bq, qp, BB * SEQ, DIM, DIM);
    gemm_nt_bias<<<gproj, 256>>>(key,   Wk, bk, kp, BB * SEQ, DIM, DIM);
    gemm_nt_bias<<<gproj, 256>>>(value, Wv, bv, vp, BB * SEQ, DIM, DIM);

    gemm_qk<<<dim3(SEQ / 128, SEQ / 128, BB * HEADS), 256>>>(qp, kp, scores);
    softmax2048<<<BB * HEADS * SEQ, 256>>>(scores);
    gemm_pv<<<dim3(1, SEQ / 128, BB * HEADS), 256>>>(scores, vp, bl);

    gemm_nt_bias<<<gproj, 256>>>(bl, Wo, bo, out, BB * SEQ, DIM, DIM);
}

// round 4
// speedup vs baseline: 3.1195x; 3.1195x over previous
#include <cuda_runtime.h>
#include <cuda_bf16.h>
#include <cstdint>

#define BB    2
#define SEQ   2048
#define DIM   1024
#define HEADS 16
#define DKH   64
#define MTOT  (BB * SEQ * DIM)

// Scratch (allocation-free rule: __device__ globals)
__device__ float g_q[MTOT];
__device__ float g_k[MTOT];
__device__ float g_v[MTOT];
__device__ float g_blend[MTOT];

// ===========================================================================
// Warp-MMA primitives (sm_80-era PTX — assembles under compute_103)
// ===========================================================================
__device__ __forceinline__ uint32_t smem_u32(const void* p) {
    uint32_t a;
    asm("{ .reg .u64 t; cvta.to.shared.u64 t, %1; cvt.u32.u64 %0, t; }"
        : "=r"(a) : "l"(p));
    return a;
}

__device__ __forceinline__ void mma16816(float* c, const uint32_t* a, const uint32_t* b) {
    asm volatile("mma.sync.aligned.m16n8k16.row.col.f32.bf16.bf16.f32 "
        "{%0,%1,%2,%3}, {%4,%5,%6,%7}, {%8,%9}, {%0,%1,%2,%3};"
        : "+f"(c[0]), "+f"(c[1]), "+f"(c[2]), "+f"(c[3])
        : "r"(a[0]), "r"(a[1]), "r"(a[2]), "r"(a[3]), "r"(b[0]), "r"(b[1]));
}

#define ST   40   // bf16 per smem row (32 data + 8 pad)
#define STB  80   // bytes per smem row

// A fragment (m16k16) via ldmatrix.x4; smem row-major [m][k], row stride STB
__device__ __forceinline__ void ldsmA4(uint32_t* r, uint32_t base, int m0, int k0, int lane) {
    uint32_t addr = base + (uint32_t)(m0 + (lane & 15)) * STB
                         + (uint32_t)(k0 + (lane >> 4) * 8) * 2;
    asm volatile("ldmatrix.sync.aligned.m8n8.x4.shared.b16 {%0,%1,%2,%3}, [%4];"
        : "=r"(r[0]), "=r"(r[1]), "=r"(r[2]), "=r"(r[3]) : "r"(addr));
}

// B fragment (k16n8) via ldmatrix.x2; smem [n][k] (k-contiguous), row stride STB
__device__ __forceinline__ void ldsmB2(uint32_t* r, uint32_t base, int n0, int k0, int lane) {
    uint32_t addr = base + (uint32_t)(n0 + (lane & 7)) * STB
                         + (uint32_t)(k0 + ((lane >> 3) & 1) * 8) * 2;
    asm volatile("ldmatrix.sync.aligned.m8n8.x2.shared.b16 {%0,%1}, [%2];"
        : "=r"(r[0]), "=r"(r[1]) : "r"(addr));
}

// ===========================================================================
// split-bf16 staging
// ===========================================================================
__device__ __forceinline__ uint32_t pack2(__nv_bfloat16 a, __nv_bfloat16 b) {
    return (uint32_t)__bfloat16_as_ushort(a) | ((uint32_t)__bfloat16_as_ushort(b) << 16);
}
__device__ __forceinline__ void split2(float a, float b, uint32_t& hi, uint32_t& lo) {
    __nv_bfloat16 ha = __float2bfloat16_rn(a);
    __nv_bfloat16 hb = __float2bfloat16_rn(b);
    __nv_bfloat16 la = __float2bfloat16_rn(a - __bfloat162float(ha));
    __nv_bfloat16 lb = __float2bfloat16_rn(b - __bfloat162float(hb));
    hi = pack2(ha, hb);
    lo = pack2(la, lb);
}

// 128 rows x 32 cols fp32 (leading dim ld) -> hi/lo bf16 tiles, row stride STB
__device__ __forceinline__ void load_tile_128x32(
    const float* __restrict__ src, int ld, char* smem_c,
    uint32_t hi_off, uint32_t lo_off, int tid)
{
#pragma unroll
    for (int it = 0; it < 4; it++) {
        int idx = tid + it * 256;       // 0..1023
        int r   = idx >> 3;             // 0..127
        int c4  = (idx & 7) * 4;        // 0..28
        float4 v = *(const float4*)(src + (size_t)r * ld + c4);
        uint32_t h01, l01, h23, l23;
        split2(v.x, v.y, h01, l01);
        split2(v.z, v.w, h23, l23);
        uint32_t off = (uint32_t)r * STB + c4 * 2;
        *(uint2*)(smem_c + hi_off + off) = make_uint2(h01, h23);
        *(uint2*)(smem_c + lo_off + off) = make_uint2(l01, l23);
    }
}

// V^T chunk: Bs[n=d (64)][k=t (32)] = V[t][d]; src points at V chunk origin, ld=DIM
__device__ __forceinline__ void load_tile_vT_64x32(
    const float* __restrict__ src, char* smem_c,
    uint32_t hi_off, uint32_t lo_off, int tid)
{
#pragma unroll
    for (int it = 0; it < 2; it++) {
        int idx = tid + it * 256;       // 0..511
        int t   = idx >> 4;             // 0..31
        int d4  = (idx & 15) * 4;       // 0..60
        float4 v = *(const float4*)(src + (size_t)t * DIM + d4);
        float vv[4] = {v.x, v.y, v.z, v.w};
#pragma unroll
        for (int j = 0; j < 4; j++) {
            __nv_bfloat16 h = __float2bfloat16_rn(vv[j]);
            __nv_bfloat16 l = __float2bfloat16_rn(vv[j] - __bfloat162float(h));
            uint32_t off = (uint32_t)(d4 + j) * STB + t * 2;
            *(__nv_bfloat16*)(smem_c + hi_off + off) = h;
            *(__nv_bfloat16*)(smem_c + lo_off + off) = l;
        }
    }
}

// Smem layout (bytes): 128-row tiles are 10240 each, 64-row tiles 5120
#define OFF_AHI 0u
#define OFF_ALO 10240u
#define OFF_BHI 20480u
#define OFF_BLO 30720u
#define SMEM_PROJ 40960
#define OFF_BHI_PV 20480u
#define OFF_BLO_PV 25600u
#define SMEM_PV   30720

// ===========================================================================
// Kernel 1: C[M,N] = A[M,K] @ W[N,K]^T + bias     (block 128x128, KC=32)
// ===========================================================================
__global__ __launch_bounds__(256, 2) void wm_gemm_nt_bias(
    const float* __restrict__ A, const float* __restrict__ W,
    const float* __restrict__ bias, float* __restrict__ C, int K, int N)
{
    extern __shared__ char smem[];
    const uint32_t sb = smem_u32(smem);
    const int tid  = threadIdx.x;
    const int wid  = tid >> 5, lane = tid & 31;
    const int bm = blockIdx.y * 128, bn = blockIdx.x * 128;
    const int wm = (wid & 3) * 32;       // warp m-origin in tile
    const int wn = (wid >> 2) * 64;      // warp n-origin in tile

    float acc[2][8][4] = {};
    const uint32_t aBase[3] = {sb + OFF_AHI, sb + OFF_AHI, sb + OFF_ALO};
    const uint32_t bBase[3] = {sb + OFF_BHI, sb + OFF_BLO, sb + OFF_BHI};

    for (int c = 0; c < (K >> 5); c++) {
        load_tile_128x32(A + (size_t)bm * K + c * 32, K, smem, OFF_AHI, OFF_ALO, tid);
        load_tile_128x32(W + (size_t)bn * K + c * 32, K, smem, OFF_BHI, OFF_BLO, tid);
        __syncthreads();
#pragma unroll
        for (int t = 0; t < 3; t++) {
#pragma unroll
            for (int k0 = 0; k0 < 32; k0 += 16) {
                uint32_t af0[4], af1[4];
                ldsmA4(af0, aBase[t], wm,      k0, lane);
                ldsmA4(af1, aBase[t], wm + 16, k0, lane);
#pragma unroll
                for (int j = 0; j < 8; j++) {
                    uint32_t bf[2];
                    ldsmB2(bf, bBase[t], wn + j * 8, k0, lane);
                    mma16816(acc[0][j], af0, bf);
                    mma16816(acc[1][j], af1, bf);
                }
            }
        }
        __syncthreads();
    }

    const int g  = lane >> 2;
    const int tg = (lane & 3) * 2;
#pragma unroll
    for (int i = 0; i < 2; i++) {
#pragma unroll
        for (int j = 0; j < 8; j++) {
            int row = bm + wm + i * 16 + g;
            int col = bn + wn + j * 8 + tg;
            float b0 = bias[col], b1 = bias[col + 1];
            *(float2*)&C[(size_t)row * N + col] =
                make_float2(acc[i][j][0] + b0, acc[i][j][1] + b1);
            *(float2*)&C[(size_t)(row + 8) * N + col] =
                make_float2(acc[i][j][2] + b0, acc[i][j][3] + b1);
        }
    }
}

// ===========================================================================
// Kernel 2: scores[bh,s,t] = 0.125 * q_h[s,:] . k_h[t,:]   (K=64 -> 2 chunks)
// ===========================================================================
__global__ __launch_bounds__(256, 2) void wm_gemm_qk(
    const float* __restrict__ q, const float* __restrict__ k,
    float* __restrict__ scores)
{
    extern __shared__ char smem[];
    const uint32_t sb = smem_u32(smem);
    const int tid  = threadIdx.x;
    const int wid  = tid >> 5, lane = tid & 31;
    const int bm = blockIdx.y * 128, bn = blockIdx.x * 128;
    const int bh = blockIdx.z;
    const int b = bh >> 4, h = bh & 15;
    const float* Asrc = q + (size_t)b * SEQ * DIM + (size_t)bm * DIM + h * DKH;
    const float* Bsrc = k + (size_t)b * SEQ * DIM + (size_t)bn * DIM + h * DKH;
    float* C = scores + (size_t)bh * SEQ * SEQ;
    const int wm = (wid & 3) * 32;
    const int wn = (wid >> 2) * 64;

    float acc[2][8][4] = {};
    const uint32_t aBase[3] = {sb + OFF_AHI, sb + OFF_AHI, sb + OFF_ALO};
    const uint32_t bBase[3] = {sb + OFF_BHI, sb + OFF_BLO, sb + OFF_BHI};

#pragma unroll
    for (int c = 0; c < 2; c++) {
        load_tile_128x32(Asrc + c * 32, DIM, smem, OFF_AHI, OFF_ALO, tid);
        load_tile_128x32(Bsrc + c * 32, DIM, smem, OFF_BHI, OFF_BLO, tid);
        __syncthreads();
#pragma unroll
        for (int t = 0; t < 3; t++) {
#pragma unroll
            for (int k0 = 0; k0 < 32; k0 += 16) {
                uint32_t af0[4], af1[4];
                ldsmA4(af0, aBase[t], wm,      k0, lane);
                ldsmA4(af1, aBase[t], wm + 16, k0, lane);
#pragma unroll
                for (int j = 0; j < 8; j++) {
                    uint32_t bf[2];
                    ldsmB2(bf, bBase[t], wn + j * 8, k0, lane);
                    mma16816(acc[0][j], af0, bf);
                    mma16816(acc[1][j], af1, bf);
                }
            }
        }
        __syncthreads();
    }

    const int g  = lane >> 2;
    const int tg = (lane & 3) * 2;
#pragma unroll
    for (int i = 0; i < 2; i++) {
#pragma unroll
        for (int j = 0; j < 8; j++) {
            int row = bm + wm + i * 16 + g;
            int col = bn + wn + j * 8 + tg;
            *(float2*)&C[(size_t)row * SEQ + col] =
                make_float2(acc[i][j][0] * 0.125f, acc[i][j][1] * 0.125f);
            *(float2*)&C[(size_t)(row + 8) * SEQ + col] =
                make_float2(acc[i][j][2] * 0.125f, acc[i][j][3] * 0.125f);
        }
    }
}

// ===========================================================================
// Kernel 3: blended[b,s,h*64+d] = sum_t P[bh,s,t] * v[b,t,h*64+d]
//           block 128(M) x 64(N), K=2048 in chunks of 32
// ===========================================================================
__global__ __launch_bounds__(256, 2) void wm_gemm_pv(
    const float* __restrict__ scores, const float* __restrict__ v,
    float* __restrict__ blend)
{
    extern __shared__ char smem[];
    const uint32_t sb = smem_u32(smem);
    const int tid  = threadIdx.x;
    const int wid  = tid >> 5, lane = tid & 31;
    const int bm = blockIdx.x * 128;
    const int bh = blockIdx.z;
    const int b = bh >> 4, h = bh & 15;
    const float* A = scores + (size_t)bh * SEQ * SEQ + (size_t)bm * SEQ;
    const float* V = v + (size_t)b * SEQ * DIM + h * DKH;
    const int wm = (wid & 3) * 32;
    const int wn = (wid >> 2) * 32;

    float acc[2][4][4] = {};
    const uint32_t aBase[3] = {sb + OFF_AHI,    sb + OFF_AHI,    sb + OFF_ALO};
    const uint32_t bBase[3] = {sb + OFF_BHI_PV, sb + OFF_BLO_PV, sb + OFF_BHI_PV};

    for (int c = 0; c < (SEQ >> 5); c++) {
        load_tile_128x32(A + c * 32, SEQ, smem, OFF_AHI, OFF_ALO, tid);
        load_tile_vT_64x32(V + (size_t)(c * 32) * DIM, smem, OFF_BHI_PV, OFF_BLO_PV, tid);
        __syncthreads();
#pragma unroll
        for (int t = 0; t < 3; t++) {
#pragma unroll
            for (int k0 = 0; k0 < 32; k0 += 16) {
                uint32_t af0[4], af1[4];
                ldsmA4(af0, aBase[t], wm,      k0, lane);
                ldsmA4(af1, aBase[t], wm + 16, k0, lane);
#pragma unroll
                for (int j = 0; j < 4; j++) {
                    uint32_t bf[2];
                    ldsmB2(bf, bBase[t], wn + j * 8, k0, lane);
                    mma16816(acc[0][j], af0, bf);
                    mma16816(acc[1][j], af1, bf);
                }
            }
        }
        __syncthreads();
    }

    const int g  = lane >> 2;
    const int tg = (lane & 3) * 2;
    float* dstb = blend + (size_t)b * SEQ * DIM + h * DKH;
#pragma unroll
    for (int i = 0; i < 2; i++) {
#pragma unroll
        for (int j = 0; j < 4; j++) {
            int row = bm + wm + i * 16 + g;
            int col = wn + j * 8 + tg;
            *(float2*)&dstb[(size_t)row * DIM + col] =
                make_float2(acc[i][j][0], acc[i][j][1]);
            *(float2*)&dstb[(size_t)(row + 8) * DIM + col] =
                make_float2(acc[i][j][2], acc[i][j][3]);
        }
    }
}

// ===========================================================================
// Row softmax, in place (row length 2048)
// ===========================================================================
__global__ __launch_bounds__(256) void softmax2048(float* __restrict__ sc)
{
    float* row = sc + (size_t)blockIdx.x * SEQ;
    const int tid = threadIdx.x;
    float4 v0 = *(const float4*)(row + tid * 4);
    float4 v1 = *(const float4*)(row + 1024 + tid * 4);

    float m = fmaxf(fmaxf(fmaxf(v0.x, v0.y), fmaxf(v0.z, v0.w)),
                    fmaxf(fmaxf(v1.x, v1.y), fmaxf(v1.z, v1.w)));
#pragma unroll
    for (int off = 16; off > 0; off >>= 1)
        m = fmaxf(m, __shfl_xor_sync(0xffffffffu, m, off));
    __shared__ float sm[8];
    if ((tid & 31) == 0) sm[tid >> 5] = m;
    __syncthreads();
    float bmax = sm[0];
#pragma unroll
    for (int w = 1; w < 8; w++) bmax = fmaxf(bmax, sm[w]);

    v0.x = __expf(v0.x - bmax); v0.y = __expf(v0.y - bmax);
    v0.z = __expf(v0.z - bmax); v0.w = __expf(v0.w - bmax);
    v1.x = __expf(v1.x - bmax); v1.y = __expf(v1.y - bmax);
    v1.z = __expf(v1.z - bmax); v1.w = __expf(v1.w - bmax);

    float s = (v0.x + v0.y + v0.z + v0.w) + (v1.x + v1.y + v1.z + v1.w);
#pragma unroll
    for (int off = 16; off > 0; off >>= 1)
        s += __shfl_xor_sync(0xffffffffu, s, off);
    __shared__ float ss[8];
    if ((tid & 31) == 0) ss[tid >> 5] = s;
    __syncthreads();
    float tot = ss[0];
#pragma unroll
    for (int w = 1; w < 8; w++) tot += ss[w];
    float inv = 1.0f / tot;

    v0.x *= inv; v0.y *= inv; v0.z *= inv; v0.w *= inv;
    v1.x *= inv; v1.y *= inv; v1.z *= inv; v1.w *= inv;
    *(float4*)(row + tid * 4) = v0;
    *(float4*)(row + 1024 + tid * 4) = v1;
}

// ===========================================================================
extern "C" void kernel_launch(void* const* d_in, const int* in_sizes, int n_in,
                              void* d_out, int out_size)
{
    const float* query = (const float*)d_in[0];
    const float* key   = (const float*)d_in[1];
    const float* value = (const float*)d_in[2];
    const float* Wq = (const float*)d_in[3];
    const float* bq = (const float*)d_in[4];
    const float* Wk = (const float*)d_in[5];
    const float* bk = (const float*)d_in[6];
    const float* Wv = (const float*)d_in[7];
    const float* bv = (const float*)d_in[8];
    const float* Wo = (const float*)d_in[9];
    const float* bo = (const float*)d_in[10];

    float* out    = (float*)d_out;
    float* scores = out + (size_t)BB * SEQ * DIM;

    float *qp, *kp, *vp, *bl;
    cudaGetSymbolAddress((void**)&qp, g_q);
    cudaGetSymbolAddress((void**)&kp, g_k);
    cudaGetSymbolAddress((void**)&vp, g_v);
    cudaGetSymbolAddress((void**)&bl, g_blend);

    dim3 gproj(DIM / 128, (BB * SEQ) / 128);   // (8, 32)
    wm_gemm_nt_bias<<<gproj, 256, SMEM_PROJ>>>(query, Wq, bq, qp, DIM, DIM);
    wm_gemm_nt_bias<<<gproj, 256, SMEM_PROJ>>>(key,   Wk, bk, kp, DIM, DIM);
    wm_gemm_nt_bias<<<gproj, 256, SMEM_PROJ>>>(value, Wv, bv, vp, DIM, DIM);

    wm_gemm_qk<<<dim3(SEQ / 128, SEQ / 128, BB * HEADS), 256, SMEM_PROJ>>>(qp, kp, scores);
    softmax2048<<<BB * HEADS * SEQ, 256>>>(scores);
    wm_gemm_pv<<<dim3(SEQ / 128, 1, BB * HEADS), 256, SMEM_PV>>>(scores, vp, bl);

    wm_gemm_nt_bias<<<gproj, 256, SMEM_PROJ>>>(bl, Wo, bo, out, DIM, DIM);
}